// round 10
// baseline (speedup 1.0000x reference)
#include <cuda_runtime.h>
#include <cuda_fp16.h>
#include <cstdint>

#define N_PTS   10242
#define C_DIM   64
#define K_DIM   9
#define NBR_DIM 7
#define O_DIM   64
#define BT_DIM  16
#define M_TOTAL (BT_DIM * N_PTS)     /* 163872 */
#define CK_DIM  (C_DIM * K_DIM)      /* 576    */

#define BM       128
#define BK       32
#define N_CHUNKS (CK_DIM / BK)       /* 18 */
#define A_LDB    80                  /* smem row pitch bytes (16B-aligned) */
#define STAGES   4

// ---------------- scratch ----------------------------------------------------
__device__ __half g_A[(size_t)M_TOTAL * CK_DIM];     // A fp16, [m][k*64+c]
__device__ uint4  g_Wfrag[2 * N_CHUNKS * 2 * 2 * 32];
__device__ int    g_any;

// ---------------- PTX helpers ------------------------------------------------
__device__ __forceinline__ uint32_t smem_u32(const void* p) {
    uint32_t a;
    asm("{ .reg .u64 t; cvta.to.shared.u64 t, %1; cvt.u32.u64 %0, t; }"
        : "=r"(a) : "l"(p));
    return a;
}

#define LDSM_X4(r, addr) \
    asm volatile("ldmatrix.sync.aligned.m8n8.x4.shared.b16 {%0,%1,%2,%3}, [%4];" \
        : "=r"((r)[0]), "=r"((r)[1]), "=r"((r)[2]), "=r"((r)[3]) : "r"(addr))

#define MMA_F16(d, a, b0, b1) \
    asm volatile("mma.sync.aligned.m16n8k16.row.col.f32.f16.f16.f32 " \
        "{%0,%1,%2,%3}, {%4,%5,%6,%7}, {%8,%9}, {%0,%1,%2,%3};" \
        : "+f"((d)[0]), "+f"((d)[1]), "+f"((d)[2]), "+f"((d)[3]) \
        : "r"((a)[0]), "r"((a)[1]), "r"((a)[2]), "r"((a)[3]), "r"(b0), "r"(b1))

// cp.async 16B with zero-fill when src_bytes < 16
#define CP_ASYNC16(dst, src, src_bytes) \
    asm volatile("cp.async.cg.shared.global [%0], [%1], 16, %2;" \
        :: "r"(dst), "l"(src), "r"(src_bytes))
#define CP_COMMIT() asm volatile("cp.async.commit_group;" ::: "memory")
#define CP_WAIT2()  asm volatile("cp.async.wait_group 2;" ::: "memory")

// ---------------- setup kernels ----------------------------------------------
__global__ void prepack_wfrag_kernel(const float* __restrict__ conv_w) {
    if (blockIdx.x == 0 && threadIdx.x == 0) g_any = 0;
    int u = blockIdx.x * 256 + threadIdx.x;
    const int TOT = 2 * N_CHUNKS * 2 * 2 * 32 * 4;
    if (u >= TOT) return;
    int j    = u & 3;
    int lane = (u >> 2) & 31;
    int g    = (u >> 7) & 1;
    int ks   = (u >> 8) & 1;
    int ch   = (u >> 9) % N_CHUNKS;
    int wn   = u / (N_CHUNKS * 512);

    int o  = wn * 32 + g * 16 + (j >> 1) * 8 + (lane >> 2);
    int kg = ch * 32 + ks * 16 + (j & 1) * 8 + (lane & 3) * 2;

    float w0 = conv_w[(o * 64 + (kg & 63)) * 9 + (kg >> 6)];
    float w1 = conv_w[(o * 64 + ((kg + 1) & 63)) * 9 + ((kg + 1) >> 6)];
    __half h0 = __float2half_rn(w0);
    __half h1 = __float2half_rn(w1);
    uint32_t packed = ((uint32_t)*(uint16_t*)&h1 << 16) | *(uint16_t*)&h0;
    ((uint32_t*)g_Wfrag)[u] = packed;
}

__global__ void detect_idx_kernel(const int* __restrict__ idx32) {
    int any = 0;
    const int pairs = N_PTS * NBR_DIM / 2;
    for (int i = blockIdx.x * 256 + threadIdx.x; i < pairs; i += gridDim.x * 256)
        any |= (idx32[2 * i + 1] != 0);
    any = __syncthreads_or(any);
    if (threadIdx.x == 0 && any) atomicOr(&g_any, 1);
}

// ---------------- phase 1: interpolation -> fp16 A ---------------------------
// Block: 256 thr = 16 rows x 16 lanes; lane handles channels 4L..4L+3.
__global__ void interp_kernel(const float* __restrict__ x,
                              const void*  __restrict__ index_raw,
                              const float* __restrict__ itp_mat) {
    __shared__ float sT[16][NBR_DIM * K_DIM];
    __shared__ int   sIdx[16][NBR_DIM];
    const int tid = threadIdx.x;
    const int m0  = blockIdx.x * 16;
    const int is64 = (g_any == 0);

    for (int i = tid; i < 16 * 63; i += 256) {
        int mi = i / 63, e = i - mi * 63;
        int n = (m0 + mi) % N_PTS;
        sT[mi][e] = itp_mat[n * 63 + e];
    }
    if (tid < 16 * NBR_DIM) {
        int mi = tid / NBR_DIM, j = tid - mi * NBR_DIM;
        int n = (m0 + mi) % N_PTS;
        int v;
        if (is64) v = (int)((const long long*)index_raw)[n * NBR_DIM + j];
        else      v = ((const int*)index_raw)[n * NBR_DIM + j];
        sIdx[mi][j] = v;
    }
    __syncthreads();

    const int lane = tid & 15;
    const int row  = tid >> 4;
    const int c0   = lane * 4;
    const int m    = m0 + row;
    const int bt   = m / N_PTS;
    const float* xb = x + (size_t)bt * N_PTS * C_DIM + c0;

    float acc[K_DIM][4];
#pragma unroll
    for (int k = 0; k < K_DIM; k++)
#pragma unroll
        for (int q = 0; q < 4; q++) acc[k][q] = 0.f;

#pragma unroll
    for (int j = 0; j < NBR_DIM; j++) {
        float4 v = *(const float4*)(xb + (size_t)sIdx[row][j] * C_DIM);
        const float* tj = &sT[row][j * K_DIM];
#pragma unroll
        for (int k = 0; k < K_DIM; k++) {
            float t = tj[k];
            acc[k][0] = fmaf(v.x, t, acc[k][0]);
            acc[k][1] = fmaf(v.y, t, acc[k][1]);
            acc[k][2] = fmaf(v.z, t, acc[k][2]);
            acc[k][3] = fmaf(v.w, t, acc[k][3]);
        }
    }

    __half* dst = g_A + (size_t)m * CK_DIM + c0;
#pragma unroll
    for (int k = 0; k < K_DIM; k++) {
        __half2 h0 = __floats2half2_rn(acc[k][0], acc[k][1]);
        __half2 h1 = __floats2half2_rn(acc[k][2], acc[k][3]);
        uint2 u;
        u.x = *(uint32_t*)&h0;
        u.y = *(uint32_t*)&h1;
        __stcs((uint2*)(dst + k * 64), u);
    }
}

// ---------------- phase 2: HMMA GEMM, cp.async 4-stage A pipeline ------------
__global__ void __launch_bounds__(256, 2)
gemm_mma_kernel(const float* __restrict__ conv_b, float* __restrict__ out) {
    __shared__ uint8_t sA[STAGES][BM * A_LDB];   // 4 x 10 KB

    const int tid = threadIdx.x;
    const int wid = tid >> 5;
    const int lid = tid & 31;
    const int wm  = wid & 3;
    const int wn  = wid >> 2;
    const int m0  = blockIdx.x * BM;

    const uint32_t aFragOff =
        (uint32_t)((wm * 32 + ((lid >> 3) & 1) * 8 + (lid & 7)) * A_LDB
                   + (lid >> 4) * 16);
    const uint32_t uA0 = smem_u32(sA);

    float acc[2][4][4];
#pragma unroll
    for (int s = 0; s < 2; s++)
#pragma unroll
        for (int n = 0; n < 4; n++)
#pragma unroll
            for (int q = 0; q < 4; q++) acc[s][n][q] = 0.f;

    // A load mapping: 512 x 16B units, 2 per thread
    const int aRow0 = tid >> 2;             // 0..63 (+64)
    const int aU    = tid & 3;
    const char* pA = (const char*)g_A;
    // per-thread validity (row beyond M_TOTAL -> zero-fill)
    int vbytes[2];
    size_t abase[2];
#pragma unroll
    for (int i = 0; i < 2; i++) {
        int m = m0 + aRow0 + i * 64;
        vbytes[i] = (m < M_TOTAL) ? 16 : 0;
        abase[i]  = (size_t)min(m, M_TOTAL - 1) * (CK_DIM * 2) + aU * 16;
    }
    const uint32_t sdst[2] = {
        uA0 + (uint32_t)(aRow0 * A_LDB + aU * 16),
        uA0 + (uint32_t)((aRow0 + 64) * A_LDB + aU * 16)
    };

    const uint4* pW = g_Wfrag + (size_t)(wn * N_CHUNKS) * 4 * 32 + lid;
    uint4 wcur[4], wnxt[4];

    // ---- prologue: chunks 0,1 in flight ----
#pragma unroll
    for (int c = 0; c < 2; c++) {
#pragma unroll
        for (int i = 0; i < 2; i++)
            CP_ASYNC16(sdst[i] + c * (BM * A_LDB), pA + abase[i] + c * 64, vbytes[i]);
        CP_COMMIT();
    }
#pragma unroll
    for (int q = 0; q < 4; q++) wcur[q] = __ldg(pW + q * 32);

    for (int ch = 0; ch < N_CHUNKS; ch++) {
        // issue chunk ch+2 (empty group when out of range keeps the count uniform)
        if (ch + 2 < N_CHUNKS) {
            const uint32_t so = ((ch + 2) & 3) * (BM * A_LDB);
#pragma unroll
            for (int i = 0; i < 2; i++)
                CP_ASYNC16(sdst[i] + so, pA + abase[i] + (ch + 2) * 64, vbytes[i]);
        }
        CP_COMMIT();
        CP_WAIT2();            // chunk ch complete (<=2 groups pending)
        __syncthreads();       // visibility + WAR (ring distance 2 bars)

        if (ch + 1 < N_CHUNKS) {
#pragma unroll
            for (int q = 0; q < 4; q++)
                wnxt[q] = __ldg(pW + ((ch + 1) * 4 + q) * 32);
        }

        const uint32_t uA = uA0 + (ch & 3) * (BM * A_LDB);
#pragma unroll
        for (int ks = 0; ks < 2; ks++) {
            const uint32_t kB = ks * 32;
            uint32_t af[2][4];
#pragma unroll
            for (int s = 0; s < 2; s++)
                LDSM_X4(af[s], uA + aFragOff + s * 16 * A_LDB + kB);
#pragma unroll
            for (int s = 0; s < 2; s++)
#pragma unroll
                for (int g = 0; g < 2; g++) {
                    const uint4 w = wcur[ks * 2 + g];
                    MMA_F16(acc[s][g * 2 + 0], af[s], w.x, w.y);
                    MMA_F16(acc[s][g * 2 + 1], af[s], w.z, w.w);
                }
        }
#pragma unroll
        for (int q = 0; q < 4; q++) wcur[q] = wnxt[q];
    }

    // ---- epilogue ----
    float bias[4][2];
#pragma unroll
    for (int n = 0; n < 4; n++) {
        int ob = wn * 32 + n * 8 + (lid & 3) * 2;
        bias[n][0] = __ldg(conv_b + ob);
        bias[n][1] = __ldg(conv_b + ob + 1);
    }
#pragma unroll
    for (int s = 0; s < 2; s++)
#pragma unroll
        for (int h = 0; h < 2; h++) {
            int m = m0 + wm * 32 + s * 16 + h * 8 + (lid >> 2);
            if (m < M_TOTAL) {
                float* op = out + (size_t)m * O_DIM + wn * 32 + (lid & 3) * 2;
#pragma unroll
                for (int n = 0; n < 4; n++) {
                    float2 v;
                    v.x = acc[s][n][h * 2 + 0] + bias[n][0];
                    v.y = acc[s][n][h * 2 + 1] + bias[n][1];
                    __stcs((float2*)(op + n * 8), v);
                }
            }
        }
}

// ---------------------------------------------------------------------------
extern "C" void kernel_launch(void* const* d_in, const int* in_sizes, int n_in,
                              void* d_out, int out_size) {
    const float* x       = (const float*)d_in[0];
    const void*  index   = d_in[1];
    const float* itp_mat = (const float*)d_in[2];
    const float* conv_w  = (const float*)d_in[3];
    const float* conv_b  = (const float*)d_in[4];
    float*       out     = (float*)d_out;

    prepack_wfrag_kernel<<<144, 256>>>(conv_w);
    detect_idx_kernel<<<64, 256>>>((const int*)index);
    interp_kernel<<<M_TOTAL / 16, 256>>>(x, index, itp_mat);
    gemm_mma_kernel<<<(M_TOTAL + BM - 1) / BM, 256>>>(conv_b, out);
}

// round 11
// speedup vs baseline: 1.3147x; 1.3147x over previous
#include <cuda_runtime.h>
#include <cuda_fp16.h>
#include <cstdint>

#define N_PTS   10242
#define C_DIM   64
#define K_DIM   9
#define NBR_DIM 7
#define O_DIM   64
#define BT_DIM  16
#define M_TOTAL (BT_DIM * N_PTS)     /* 163872 */
#define CK_DIM  (C_DIM * K_DIM)      /* 576    */

#define BM       128
#define BK       32
#define N_CHUNKS (CK_DIM / BK)       /* 18 */
#define A_LDB    80                  /* smem row pitch bytes: 64 B + 16 pad */

// ---------------- scratch ----------------------------------------------------
__device__ __half g_A[(size_t)M_TOTAL * CK_DIM];     // A fp16, [m][k*64+c]
__device__ uint4  g_Wfrag[2 * N_CHUNKS * 2 * 2 * 32];
__device__ int    g_any;

// ---------------- PTX helpers ------------------------------------------------
__device__ __forceinline__ uint32_t smem_u32(const void* p) {
    uint32_t a;
    asm("{ .reg .u64 t; cvta.to.shared.u64 t, %1; cvt.u32.u64 %0, t; }"
        : "=r"(a) : "l"(p));
    return a;
}

#define LDSM_X4(r, addr) \
    asm volatile("ldmatrix.sync.aligned.m8n8.x4.shared.b16 {%0,%1,%2,%3}, [%4];" \
        : "=r"((r)[0]), "=r"((r)[1]), "=r"((r)[2]), "=r"((r)[3]) : "r"(addr))

#define MMA_F16(d, a, b0, b1) \
    asm volatile("mma.sync.aligned.m16n8k16.row.col.f32.f16.f16.f32 " \
        "{%0,%1,%2,%3}, {%4,%5,%6,%7}, {%8,%9}, {%0,%1,%2,%3};" \
        : "+f"((d)[0]), "+f"((d)[1]), "+f"((d)[2]), "+f"((d)[3]) \
        : "r"((a)[0]), "r"((a)[1]), "r"((a)[2]), "r"((a)[3]), "r"(b0), "r"(b1))

// packed fp32x2 fma: d = a*b + d  (exact fp32 math, 1 issue slot for 2 FMAs)
#define FFMA2(d, a, b) \
    asm("fma.rn.f32x2 %0, %1, %2, %0;" : "+l"(d) : "l"(a), "l"(b))

// ---------------- setup kernels ----------------------------------------------
__global__ void prepack_wfrag_kernel(const float* __restrict__ conv_w) {
    if (blockIdx.x == 0 && threadIdx.x == 0) g_any = 0;
    int u = blockIdx.x * 256 + threadIdx.x;
    const int TOT = 2 * N_CHUNKS * 2 * 2 * 32 * 4;
    if (u >= TOT) return;
    int j    = u & 3;
    int lane = (u >> 2) & 31;
    int g    = (u >> 7) & 1;
    int ks   = (u >> 8) & 1;
    int ch   = (u >> 9) % N_CHUNKS;
    int wn   = u / (N_CHUNKS * 512);

    int o  = wn * 32 + g * 16 + (j >> 1) * 8 + (lane >> 2);
    int kg = ch * 32 + ks * 16 + (j & 1) * 8 + (lane & 3) * 2;

    float w0 = conv_w[(o * 64 + (kg & 63)) * 9 + (kg >> 6)];
    float w1 = conv_w[(o * 64 + ((kg + 1) & 63)) * 9 + ((kg + 1) >> 6)];
    __half h0 = __float2half_rn(w0);
    __half h1 = __float2half_rn(w1);
    uint32_t packed = ((uint32_t)*(uint16_t*)&h1 << 16) | *(uint16_t*)&h0;
    ((uint32_t*)g_Wfrag)[u] = packed;
}

__global__ void detect_idx_kernel(const int* __restrict__ idx32) {
    int any = 0;
    const int pairs = N_PTS * NBR_DIM / 2;
    for (int i = blockIdx.x * 256 + threadIdx.x; i < pairs; i += gridDim.x * 256)
        any |= (idx32[2 * i + 1] != 0);
    any = __syncthreads_or(any);
    if (threadIdx.x == 0 && any) atomicOr(&g_any, 1);
}

// ---------------- phase 1: interpolation -> fp16 A ---------------------------
// Block: 256 thr = 16 rows x 16 lanes; lane handles channels 4L..4L+3.
// T stored as duplicated pairs: sTd[row][j][p] = (t2p, t2p, t2p+1, t2p+1),
// so one LDS.128 delivers two packed f32x2 multiplier operands.
__global__ void interp_kernel(const float* __restrict__ x,
                              const void*  __restrict__ index_raw,
                              const float* __restrict__ itp_mat) {
    __shared__ float4 sTd[16][NBR_DIM][5];    // 8960 B
    __shared__ int    sIdx[16][NBR_DIM];
    const int tid = threadIdx.x;
    const int m0  = blockIdx.x * 16;
    const int is64 = (g_any == 0);

    for (int i = tid; i < 16 * NBR_DIM * 5; i += 256) {
        int p  = i % 5;
        int j  = (i / 5) % NBR_DIM;
        int mi = i / (5 * NBR_DIM);
        int n  = (m0 + mi) % N_PTS;
        const float* tp = itp_mat + n * 63 + j * K_DIM;
        float ta = tp[2 * p];
        float tb = (2 * p + 1 < K_DIM) ? tp[2 * p + 1] : 0.f;
        sTd[mi][j][p] = make_float4(ta, ta, tb, tb);
    }
    if (tid < 16 * NBR_DIM) {
        int mi = tid / NBR_DIM, j = tid - mi * NBR_DIM;
        int n = (m0 + mi) % N_PTS;
        int v;
        if (is64) v = (int)((const long long*)index_raw)[n * NBR_DIM + j];
        else      v = ((const int*)index_raw)[n * NBR_DIM + j];
        sIdx[mi][j] = v;
    }
    __syncthreads();

    const int lane = tid & 15;
    const int row  = tid >> 4;
    const int c0   = lane * 4;
    const int m    = m0 + row;                 // grid exact
    const int bt   = m / N_PTS;
    const float* xb = x + (size_t)bt * N_PTS * C_DIM + c0;

    // acc2[k][0] = packed (c0,c1); acc2[k][1] = packed (c2,c3). 0ull == (0f,0f).
    unsigned long long acc2[K_DIM][2];
#pragma unroll
    for (int k = 0; k < K_DIM; k++) { acc2[k][0] = 0ull; acc2[k][1] = 0ull; }

#pragma unroll
    for (int j = 0; j < NBR_DIM; j++) {
        // gather 4 channels as two pre-packed f32x2 operands
        ulonglong2 v = *(const ulonglong2*)(xb + (size_t)sIdx[row][j] * C_DIM);
#pragma unroll
        for (int p = 0; p < 5; p++) {
            ulonglong2 tq = *(const ulonglong2*)(&sTd[row][j][p]);
            FFMA2(acc2[2 * p][0], v.x, tq.x);
            FFMA2(acc2[2 * p][1], v.y, tq.x);
            if (p < 4) {
                FFMA2(acc2[2 * p + 1][0], v.x, tq.y);
                FFMA2(acc2[2 * p + 1][1], v.y, tq.y);
            }
        }
    }

    __half* dst = g_A + (size_t)m * CK_DIM + c0;
#pragma unroll
    for (int k = 0; k < K_DIM; k++) {
        uint32_t l0, h0, l1, h1;
        asm("mov.b64 {%0, %1}, %2;" : "=r"(l0), "=r"(h0) : "l"(acc2[k][0]));
        asm("mov.b64 {%0, %1}, %2;" : "=r"(l1), "=r"(h1) : "l"(acc2[k][1]));
        __half2 p0 = __floats2half2_rn(__uint_as_float(l0), __uint_as_float(h0));
        __half2 p1 = __floats2half2_rn(__uint_as_float(l1), __uint_as_float(h1));
        uint2 u;
        u.x = *(uint32_t*)&p0;
        u.y = *(uint32_t*)&p1;
        __stcs((uint2*)(dst + k * 64), u);     // streaming store
    }
}

// ---------------- phase 2: HMMA fp16 GEMM (round-9 version, unchanged) -------
__global__ void __launch_bounds__(256, 2)
gemm_mma_kernel(const float* __restrict__ conv_b, float* __restrict__ out) {
    __shared__ uint8_t sA[BM * A_LDB];          // 10 KB

    const int tid = threadIdx.x;
    const int wid = tid >> 5;
    const int lid = tid & 31;
    const int wm  = wid & 3;
    const int wn  = wid >> 2;
    const int m0  = blockIdx.x * BM;

    const uint32_t aFragOff =
        (uint32_t)((wm * 32 + ((lid >> 3) & 1) * 8 + (lid & 7)) * A_LDB
                   + (lid >> 4) * 16);
    const uint32_t uA = smem_u32(sA);

    float acc[2][4][4];
#pragma unroll
    for (int s = 0; s < 2; s++)
#pragma unroll
        for (int n = 0; n < 4; n++)
#pragma unroll
            for (int q = 0; q < 4; q++) acc[s][n][q] = 0.f;

    const int aRow0 = tid >> 2;
    const int aU    = tid & 3;
    const char* pA = (const char*)g_A;
    const uint4* pW = g_Wfrag + (size_t)(wn * N_CHUNKS) * 4 * 32 + lid;

    uint4 rA[2], wcur[4], wnxt[4];
    const uint4 Z4 = make_uint4(0, 0, 0, 0);

#pragma unroll
    for (int i = 0; i < 2; i++) {
        int m = m0 + aRow0 + i * 64;
        size_t off = (size_t)m * (CK_DIM * 2) + aU * 16;
        rA[i] = (m < M_TOTAL) ? __ldcs((const uint4*)(pA + off)) : Z4;
    }
#pragma unroll
    for (int q = 0; q < 4; q++) wcur[q] = __ldg(pW + q * 32);

    for (int ch = 0; ch < N_CHUNKS; ch++) {
        __syncthreads();
#pragma unroll
        for (int i = 0; i < 2; i++)
            *(uint4*)(sA + (aRow0 + i * 64) * A_LDB + aU * 16) = rA[i];
        *(uint4*)(sA + (aRow0 + 64) * A_LDB + aU * 16) = rA[1];
        __syncthreads();

        if (ch + 1 < N_CHUNKS) {
            const int ccB = (ch + 1) * BK * 2;
#pragma unroll
            for (int i = 0; i < 2; i++) {
                int m = m0 + aRow0 + i * 64;
                size_t off = (size_t)m * (CK_DIM * 2) + ccB + aU * 16;
                rA[i] = (m < M_TOTAL) ? __ldcs((const uint4*)(pA + off)) : Z4;
            }
#pragma unroll
            for (int q = 0; q < 4; q++)
                wnxt[q] = __ldg(pW + ((ch + 1) * 4 + q) * 32);
        }

#pragma unroll
        for (int ks = 0; ks < 2; ks++) {
            const uint32_t kB = ks * 32;
            uint32_t af[2][4];
#pragma unroll
            for (int s = 0; s < 2; s++)
                LDSM_X4(af[s], uA + aFragOff + s * 16 * A_LDB + kB);
#pragma unroll
            for (int s = 0; s < 2; s++)
#pragma unroll
                for (int g = 0; g < 2; g++) {
                    const uint4 w = wcur[ks * 2 + g];
                    MMA_F16(acc[s][g * 2 + 0], af[s], w.x, w.y);
                    MMA_F16(acc[s][g * 2 + 1], af[s], w.z, w.w);
                }
        }
#pragma unroll
        for (int q = 0; q < 4; q++) wcur[q] = wnxt[q];
    }

    // ---- epilogue ----
    float bias[4][2];
#pragma unroll
    for (int n = 0; n < 4; n++) {
        int ob = wn * 32 + n * 8 + (lid & 3) * 2;
        bias[n][0] = __ldg(conv_b + ob);
        bias[n][1] = __ldg(conv_b + ob + 1);
    }
#pragma unroll
    for (int s = 0; s < 2; s++)
#pragma unroll
        for (int h = 0; h < 2; h++) {
            int m = m0 + wm * 32 + s * 16 + h * 8 + (lid >> 2);
            if (m < M_TOTAL) {
                float* op = out + (size_t)m * O_DIM + wn * 32 + (lid & 3) * 2;
#pragma unroll
                for (int n = 0; n < 4; n++) {
                    float2 v;
                    v.x = acc[s][n][h * 2 + 0] + bias[n][0];
                    v.y = acc[s][n][h * 2 + 1] + bias[n][1];
                    *(float2*)(op + n * 8) = v;
                }
            }
        }
}

// ---------------------------------------------------------------------------
extern "C" void kernel_launch(void* const* d_in, const int* in_sizes, int n_in,
                              void* d_out, int out_size) {
    const float* x       = (const float*)d_in[0];
    const void*  index   = d_in[1];
    const float* itp_mat = (const float*)d_in[2];
    const float* conv_w  = (const float*)d_in[3];
    const float* conv_b  = (const float*)d_in[4];
    float*       out     = (float*)d_out;

    prepack_wfrag_kernel<<<144, 256>>>(conv_w);
    detect_idx_kernel<<<64, 256>>>((const int*)index);
    interp_kernel<<<M_TOTAL / 16, 256>>>(x, index, itp_mat);
    gemm_mma_kernel<<<(M_TOTAL + BM - 1) / BM, 256>>>(conv_b, out);
}

// round 13
// speedup vs baseline: 1.3184x; 1.0028x over previous
#include <cuda_runtime.h>
#include <cuda_fp16.h>
#include <cstdint>

#define N_PTS   10242
#define C_DIM   64
#define K_DIM   9
#define NBR_DIM 7
#define O_DIM   64
#define BT_DIM  16
#define M_TOTAL (BT_DIM * N_PTS)     /* 163872 */
#define CK_DIM  (C_DIM * K_DIM)      /* 576    */

#define BM       128
#define N_CHUNKS 18                  /* K chunks of 32 */
#define N_TILES  ((M_TOTAL + BM - 1) / BM)   /* 1281 */
/* per (tile, wm, s) block: 36 (ch,ks) planes x 4 regs x 32 lanes = 4608 u32 */
#define SUB_U32  4608

// ---------------- scratch ----------------------------------------------------
// A in MMA A-fragment plane layout:
// [tile][wm][s] blocks of SUB_U32; within: ((ch*2+ks)*4 + reg)*32 + lane
__device__ uint32_t g_Afrag[(size_t)N_TILES * 8 * SUB_U32];
__device__ uint4    g_Wfrag[2 * N_CHUNKS * 2 * 2 * 32];
__device__ int      g_any;

// ---------------- PTX helpers ------------------------------------------------
#define MMA_F16(d, a, b0, b1) \
    asm volatile("mma.sync.aligned.m16n8k16.row.col.f32.f16.f16.f32 " \
        "{%0,%1,%2,%3}, {%4,%5,%6,%7}, {%8,%9}, {%0,%1,%2,%3};" \
        : "+f"((d)[0]), "+f"((d)[1]), "+f"((d)[2]), "+f"((d)[3]) \
        : "r"((a)[0]), "r"((a)[1]), "r"((a)[2]), "r"((a)[3]), "r"(b0), "r"(b1))

// packed fp32x2 fma: d = a*b + d
#define FFMA2(d, a, b) \
    asm("fma.rn.f32x2 %0, %1, %2, %0;" : "+l"(d) : "l"(a), "l"(b))

// ---------------- setup kernels ----------------------------------------------
__global__ void prepack_wfrag_kernel(const float* __restrict__ conv_w) {
    if (blockIdx.x == 0 && threadIdx.x == 0) g_any = 0;
    int u = blockIdx.x * 256 + threadIdx.x;
    const int TOT = 2 * N_CHUNKS * 2 * 2 * 32 * 4;
    if (u >= TOT) return;
    int j    = u & 3;
    int lane = (u >> 2) & 31;
    int g    = (u >> 7) & 1;
    int ks   = (u >> 8) & 1;
    int ch   = (u >> 9) % N_CHUNKS;
    int wn   = u / (N_CHUNKS * 512);

    int o  = wn * 32 + g * 16 + (j >> 1) * 8 + (lane >> 2);
    int kg = ch * 32 + ks * 16 + (j & 1) * 8 + (lane & 3) * 2;

    float w0 = conv_w[(o * 64 + (kg & 63)) * 9 + (kg >> 6)];
    float w1 = conv_w[(o * 64 + ((kg + 1) & 63)) * 9 + ((kg + 1) >> 6)];
    __half h0 = __float2half_rn(w0);
    __half h1 = __float2half_rn(w1);
    uint32_t packed = ((uint32_t)*(uint16_t*)&h1 << 16) | *(uint16_t*)&h0;
    ((uint32_t*)g_Wfrag)[u] = packed;
}

__global__ void detect_idx_kernel(const int* __restrict__ idx32) {
    int any = 0;
    const int pairs = N_PTS * NBR_DIM / 2;
    for (int i = blockIdx.x * 256 + threadIdx.x; i < pairs; i += gridDim.x * 256)
        any |= (idx32[2 * i + 1] != 0);
    any = __syncthreads_or(any);
    if (threadIdx.x == 0 && any) atomicOr(&g_any, 1);
}

// ---------------- phase 1: interpolation -> A fragments ----------------------
// Block: 256 thr = 16 rows x 16 lanes; block = one (tile, wm, s) subtile.
// lane handles channels 4L..4L+3; per k the two half2 regs land in adjacent
// lanes of one reg-plane -> single 8B store.
__global__ void interp_kernel(const float* __restrict__ x,
                              const void*  __restrict__ index_raw,
                              const float* __restrict__ itp_mat) {
    __shared__ float4 sTd[16][NBR_DIM][5];
    __shared__ int    sIdx[16][NBR_DIM];
    const int tid = threadIdx.x;
    const int m0  = blockIdx.x * 16;
    const int is64 = (g_any == 0);

    for (int i = tid; i < 16 * NBR_DIM * 5; i += 256) {
        int p  = i % 5;
        int j  = (i / 5) % NBR_DIM;
        int mi = i / (5 * NBR_DIM);
        int n  = (m0 + mi) % N_PTS;
        const float* tp = itp_mat + n * 63 + j * K_DIM;
        float ta = tp[2 * p];
        float tb = (2 * p + 1 < K_DIM) ? tp[2 * p + 1] : 0.f;
        sTd[mi][j][p] = make_float4(ta, ta, tb, tb);
    }
    if (tid < 16 * NBR_DIM) {
        int mi = tid / NBR_DIM, j = tid - mi * NBR_DIM;
        int n = (m0 + mi) % N_PTS;
        int v;
        if (is64) v = (int)((const long long*)index_raw)[n * NBR_DIM + j];
        else      v = ((const int*)index_raw)[n * NBR_DIM + j];
        sIdx[mi][j] = v;
    }
    __syncthreads();

    const int lane = tid & 15;
    const int row  = tid >> 4;                 // r within 16-row subtile
    const int c0   = lane * 4;
    const int m    = m0 + row;
    const int bt   = m / N_PTS;
    const float* xb = x + (size_t)bt * N_PTS * C_DIM + c0;

    unsigned long long acc2[K_DIM][2];
#pragma unroll
    for (int k = 0; k < K_DIM; k++) { acc2[k][0] = 0ull; acc2[k][1] = 0ull; }

#pragma unroll
    for (int j = 0; j < NBR_DIM; j++) {
        ulonglong2 v = *(const ulonglong2*)(xb + (size_t)sIdx[row][j] * C_DIM);
#pragma unroll
        for (int p = 0; p < 5; p++) {
            ulonglong2 tq = *(const ulonglong2*)(&sTd[row][j][p]);
            FFMA2(acc2[2 * p][0], v.x, tq.x);
            FFMA2(acc2[2 * p][1], v.y, tq.x);
            if (p < 4) {
                FFMA2(acc2[2 * p + 1][0], v.x, tq.y);
                FFMA2(acc2[2 * p + 1][1], v.y, tq.y);
            }
        }
    }

    // ---- fragment-layout store ----
    // per-thread constants:
    const int cc5  = c0 >> 5;                  // chunk parity from c
    const int ks   = (c0 >> 4) & 1;
    const int regq = ((c0 & 15) >= 8) ? 2 : 0;
    const int rbit = (row >= 8) ? 1 : 0;
    const int cst  = (cc5 * 2 + ks) * 4 + rbit + regq;      // plane idx offset
    const int lnp  = (row & 7) * 4 + ((c0 & 7) >> 1);       // lane slot (even)
    uint32_t* dbase = g_Afrag + (size_t)blockIdx.x * SUB_U32 + lnp;

#pragma unroll
    for (int k = 0; k < K_DIM; k++) {
        uint32_t l0, h0, l1, h1;
        asm("mov.b64 {%0, %1}, %2;" : "=r"(l0), "=r"(h0) : "l"(acc2[k][0]));
        asm("mov.b64 {%0, %1}, %2;" : "=r"(l1), "=r"(h1) : "l"(acc2[k][1]));
        __half2 p0 = __floats2half2_rn(__uint_as_float(l0), __uint_as_float(h0));
        __half2 p1 = __floats2half2_rn(__uint_as_float(l1), __uint_as_float(h1));
        uint2 u;
        u.x = *(uint32_t*)&p0;                 // (c0, c0+1) -> lane lnp
        u.y = *(uint32_t*)&p1;                 // (c0+2, c0+3) -> lane lnp+1
        __stcs((uint2*)(dbase + (cst + k * 16) * 32), u);
    }
}

// ---------------- phase 2: HMMA GEMM, pure LDG fragments (no smem) -----------
__global__ void __launch_bounds__(256, 2)
gemm_mma_kernel(const float* __restrict__ conv_b, float* __restrict__ out) {
    const int tid = threadIdx.x;
    const int wid = tid >> 5;
    const int lid = tid & 31;
    const int wm  = wid & 3;
    const int wn  = wid >> 2;
    const int m0  = blockIdx.x * BM;

    float acc[2][4][4];
#pragma unroll
    for (int s = 0; s < 2; s++)
#pragma unroll
        for (int n = 0; n < 4; n++)
#pragma unroll
            for (int q = 0; q < 4; q++) acc[s][n][q] = 0.f;

    // A fragment base for this warp's (tile, wm); s stride = SUB_U32
    const uint32_t* pA = g_Afrag
        + (size_t)(blockIdx.x * 8 + wm * 2) * SUB_U32 + lid;
    const uint4* pW = g_Wfrag + (size_t)(wn * N_CHUNKS) * 4 * 32 + lid;

    uint32_t Ac[2][2][4], An[2][2][4];         // [s][ks][reg]
    uint4 wcur[4], wnxt[4];

    // ---- prologue: chunk 0 ----
#pragma unroll
    for (int s = 0; s < 2; s++)
#pragma unroll
        for (int ks = 0; ks < 2; ks++)
#pragma unroll
            for (int r = 0; r < 4; r++)
                Ac[s][ks][r] = __ldcs(pA + s * SUB_U32 + ks * 128 + r * 32);
#pragma unroll
    for (int q = 0; q < 4; q++) wcur[q] = __ldg(pW + q * 32);

    for (int ch = 0; ch < N_CHUNKS; ch++) {
        if (ch + 1 < N_CHUNKS) {
            const int co = (ch + 1) * 256;     // (ch*2+ks)*128 with ks folded
#pragma unroll
            for (int s = 0; s < 2; s++)
#pragma unroll
                for (int ks = 0; ks < 2; ks++)
#pragma unroll
                    for (int r = 0; r < 4; r++)
                        An[s][ks][r] = __ldcs(pA + s * SUB_U32 + co + ks * 128 + r * 32);
#pragma unroll
            for (int q = 0; q < 4; q++)
                wnxt[q] = __ldg(pW + ((ch + 1) * 4 + q) * 32);
        }

#pragma unroll
        for (int ks = 0; ks < 2; ks++)
#pragma unroll
            for (int s = 0; s < 2; s++)
#pragma unroll
                for (int g = 0; g < 2; g++) {
                    const uint4 w = wcur[ks * 2 + g];
                    MMA_F16(acc[s][g * 2 + 0], Ac[s][ks], w.x, w.y);
                    MMA_F16(acc[s][g * 2 + 1], Ac[s][ks], w.z, w.w);
                }

#pragma unroll
        for (int s = 0; s < 2; s++)
#pragma unroll
            for (int ks = 0; ks < 2; ks++)
#pragma unroll
                for (int r = 0; r < 4; r++)
                    Ac[s][ks][r] = An[s][ks][r];
#pragma unroll
        for (int q = 0; q < 4; q++) wcur[q] = wnxt[q];
    }

    // ---- epilogue ----
    float bias[4][2];
#pragma unroll
    for (int n = 0; n < 4; n++) {
        int ob = wn * 32 + n * 8 + (lid & 3) * 2;
        bias[n][0] = __ldg(conv_b + ob);
        bias[n][1] = __ldg(conv_b + ob + 1);
    }
#pragma unroll
    for (int s = 0; s < 2; s++)
#pragma unroll
        for (int h = 0; h < 2; h++) {
            int m = m0 + wm * 32 + s * 16 + h * 8 + (lid >> 2);
            if (m < M_TOTAL) {
                float* op = out + (size_t)m * O_DIM + wn * 32 + (lid & 3) * 2;
#pragma unroll
                for (int n = 0; n < 4; n++) {
                    float2 v;
                    v.x = acc[s][n][h * 2 + 0] + bias[n][0];
                    v.y = acc[s][n][h * 2 + 1] + bias[n][1];
                    *(float2*)(op + n * 8) = v;
                }
            }
        }
}

// ---------------------------------------------------------------------------
extern "C" void kernel_launch(void* const* d_in, const int* in_sizes, int n_in,
                              void* d_out, int out_size) {
    const float* x       = (const float*)d_in[0];
    const void*  index   = d_in[1];
    const float* itp_mat = (const float*)d_in[2];
    const float* conv_w  = (const float*)d_in[3];
    const float* conv_b  = (const float*)d_in[4];
    float*       out     = (float*)d_out;

    prepack_wfrag_kernel<<<144, 256>>>(conv_w);
    detect_idx_kernel<<<64, 256>>>((const int*)index);
    interp_kernel<<<M_TOTAL / 16, 256>>>(x, index, itp_mat);
    gemm_mma_kernel<<<N_TILES, 256>>>(conv_b, out);
}